// round 1
// baseline (speedup 1.0000x reference)
#include <cuda_runtime.h>
#include <cuda_bf16.h>
#include <math.h>

// ---------------------------------------------------------------------------
// Problem constants
// ---------------------------------------------------------------------------
#define D_MODEL   512
#define D_STATE   128
#define D_CONV    4
#define HEADDIM   64
#define D_INNER   1024
#define NHEADS    16
#define CONV_DIM  1280           // D_INNER + 2*D_STATE
#define D_IN_PROJ 2320           // 2*D_INNER + 2*D_STATE + NHEADS
#define LSEQ      64             // sequence length (W for h-pass, H for v-pass)
#define NSEQ      128            // number of sequences per mamba call (B*H or B*W)
#define NTOK      8192           // NSEQ * LSEQ
#define EPS       1e-5f

// ---------------------------------------------------------------------------
// Device scratch (static globals: no allocation at runtime)
// ---------------------------------------------------------------------------
__device__ float g_xv   [(size_t)NTOK * D_MODEL];     // transposed input for v-pass
__device__ float g_zx   [(size_t)NTOK * D_IN_PROJ];   // in-proj output
__device__ float g_xbc  [(size_t)NTOK * CONV_DIM];    // conv+silu output
__device__ float g_y    [(size_t)NTOK * D_INNER];     // SSM output / normed
__device__ float g_hout [(size_t)NTOK * D_MODEL];     // h-direction out-proj
__device__ float g_vout [(size_t)NTOK * D_MODEL];     // v-direction out-proj
__device__ float g_cat  [(size_t)NTOK * D_INNER];     // [v1 | h1] concat
__device__ float g_fceff[(size_t)D_MODEL * D_INNER];  // pre-summed fc weights

// ---------------------------------------------------------------------------
// SGEMM: C[m][n] = sum_k A[m][k] * W[n][k] (+ bias[n])
// A: MxK row-major, W: NxK row-major. 128x128 block, 8x8 per thread, BK=8.
// M must be a multiple of 128 (always 8192 here). N is guarded.
// ---------------------------------------------------------------------------
__global__ __launch_bounds__(256)
void sgemm_nt_kernel(const float* __restrict__ A, const float* __restrict__ W,
                     float* __restrict__ C, int M, int N, int K,
                     const float* __restrict__ bias)
{
    __shared__ __align__(16) float As[8][128];
    __shared__ __align__(16) float Ws[8][128];

    const int tid  = threadIdx.x;
    const int m0   = blockIdx.y * 128;
    const int n0   = blockIdx.x * 128;
    const int row  = tid >> 1;           // 0..127
    const int quad = (tid & 1) * 4;      // 0 or 4
    const int ty   = tid >> 4;           // 0..15
    const int tx   = tid & 15;           // 0..15

    float acc[8][8];
#pragma unroll
    for (int i = 0; i < 8; ++i)
#pragma unroll
        for (int j = 0; j < 8; ++j) acc[i][j] = 0.f;

    for (int k0 = 0; k0 < K; k0 += 8) {
        // load A tile (always in range: M % 128 == 0)
        float4 av = *(const float4*)(A + (size_t)(m0 + row) * K + k0 + quad);
        As[quad + 0][row] = av.x;
        As[quad + 1][row] = av.y;
        As[quad + 2][row] = av.z;
        As[quad + 3][row] = av.w;
        // load W tile (guard N)
        float4 wv = make_float4(0.f, 0.f, 0.f, 0.f);
        int wn = n0 + row;
        if (wn < N) wv = *(const float4*)(W + (size_t)wn * K + k0 + quad);
        Ws[quad + 0][row] = wv.x;
        Ws[quad + 1][row] = wv.y;
        Ws[quad + 2][row] = wv.z;
        Ws[quad + 3][row] = wv.w;
        __syncthreads();

#pragma unroll
        for (int k = 0; k < 8; ++k) {
            float af[8], wf[8];
            *(float4*)(af)     = *(const float4*)&As[k][ty * 8];
            *(float4*)(af + 4) = *(const float4*)&As[k][ty * 8 + 4];
            *(float4*)(wf)     = *(const float4*)&Ws[k][tx * 8];
            *(float4*)(wf + 4) = *(const float4*)&Ws[k][tx * 8 + 4];
#pragma unroll
            for (int i = 0; i < 8; ++i)
#pragma unroll
                for (int j = 0; j < 8; ++j)
                    acc[i][j] = fmaf(af[i], wf[j], acc[i][j]);
        }
        __syncthreads();
    }

#pragma unroll
    for (int i = 0; i < 8; ++i) {
        int m = m0 + ty * 8 + i;
#pragma unroll
        for (int j = 0; j < 8; ++j) {
            int n = n0 + tx * 8 + j;
            if (n < N) {
                float v = acc[i][j];
                if (bias) v += bias[n];
                C[(size_t)m * N + n] = v;
            }
        }
    }
}

// ---------------------------------------------------------------------------
// Depthwise causal conv (width 4) + SiLU over the xBC slice of zxbcdt.
// thread = (seq, channel), rolls over t.
// ---------------------------------------------------------------------------
__global__ void conv_silu_kernel(const float* __restrict__ zx,
                                 const float* __restrict__ cw,
                                 const float* __restrict__ cb,
                                 float* __restrict__ xbc)
{
    int idx = blockIdx.x * blockDim.x + threadIdx.x;
    if (idx >= NSEQ * CONV_DIM) return;
    int seq = idx / CONV_DIM;
    int c   = idx - seq * CONV_DIM;

    float w0 = cw[c * 4 + 0], w1 = cw[c * 4 + 1];
    float w2 = cw[c * 4 + 2], w3 = cw[c * 4 + 3];
    float b  = cb[c];

    size_t ibase = (size_t)seq * LSEQ * D_IN_PROJ + D_INNER + c;
    size_t obase = (size_t)seq * LSEQ * CONV_DIM + c;

    float x0 = 0.f, x1 = 0.f, x2 = 0.f;
    for (int t = 0; t < LSEQ; ++t) {
        float xt = zx[ibase + (size_t)t * D_IN_PROJ];
        float v  = x0 * w0 + x1 * w1 + x2 * w2 + xt * w3 + b;
        xbc[obase + (size_t)t * CONV_DIM] = v / (1.f + expf(-v));
        x0 = x1; x1 = x2; x2 = xt;
    }
}

// ---------------------------------------------------------------------------
// SSM kernel: one block per (seq, head). Quadratic (l=64) form:
//   W[t][s] = (C[t] . B[s]) * exp(cs[t]-cs[s]) * dt[s]   for s<=t
//   y[t][p] = sum_s W[t][s] * x[s][p] + D * x[t][p]
// ---------------------------------------------------------------------------
#define BC_STRIDE 129
#define XS_STRIDE 65
#define SSM_SMEM_FLOATS (2 * 64 * BC_STRIDE + 2 * 64 * XS_STRIDE + 128)
#define SSM_SMEM_BYTES  (SSM_SMEM_FLOATS * 4)

__global__ __launch_bounds__(256)
void ssm_kernel(const float* __restrict__ zx, const float* __restrict__ xbc,
                const float* __restrict__ A_log, const float* __restrict__ dt_bias,
                const float* __restrict__ Dp, float* __restrict__ y)
{
    extern __shared__ float sm[];
    float* Bs  = sm;
    float* Cs  = Bs + 64 * BC_STRIDE;
    float* xs  = Cs + 64 * BC_STRIDE;
    float* Wts = xs + 64 * XS_STRIDE;
    float* dts = Wts + 64 * XS_STRIDE;
    float* css = dts + 64;

    const int blk = blockIdx.x;
    const int seq = blk >> 4;
    const int h   = blk & 15;
    const int tid = threadIdx.x;

    for (int i = tid; i < 64 * 128; i += 256) {
        int t = i >> 7, n = i & 127;
        size_t base = (size_t)(seq * LSEQ + t) * CONV_DIM;
        Bs[t * BC_STRIDE + n] = xbc[base + D_INNER + n];
        Cs[t * BC_STRIDE + n] = xbc[base + D_INNER + D_STATE + n];
    }
    for (int i = tid; i < 64 * 64; i += 256) {
        int t = i >> 6, p = i & 63;
        xs[t * XS_STRIDE + p] = xbc[(size_t)(seq * LSEQ + t) * CONV_DIM + h * HEADDIM + p];
    }
    if (tid < 64) {
        float raw = zx[(size_t)(seq * LSEQ + tid) * D_IN_PROJ + (D_INNER + CONV_DIM) + h]
                    + dt_bias[h];
        dts[tid] = (raw > 20.f) ? raw : log1pf(expf(raw));
    }
    __syncthreads();
    if (tid == 0) {
        float a = -expf(A_log[h]);
        float run = 0.f;
        for (int t = 0; t < 64; ++t) { run += dts[t] * a; css[t] = run; }
    }
    __syncthreads();

    // W matrix: 4096 entries, 16 per thread, warp-uniform t for conflict-free smem
#pragma unroll 1
    for (int j = 0; j < 16; ++j) {
        int idx = j * 256 + tid;
        int t = idx >> 6, s = idx & 63;
        float val = 0.f;
        if (s <= t) {
            float dot = 0.f;
#pragma unroll 8
            for (int n = 0; n < 128; ++n)
                dot = fmaf(Cs[t * BC_STRIDE + n], Bs[s * BC_STRIDE + n], dot);
            val = dot * expf(css[t] - css[s]) * dts[s];
        }
        Wts[t * XS_STRIDE + s] = val;
    }
    __syncthreads();

    const float dcoef = Dp[h];
#pragma unroll 1
    for (int j = 0; j < 16; ++j) {
        int idx = j * 256 + tid;
        int t = idx >> 6, p = idx & 63;
        float acc = dcoef * xs[t * XS_STRIDE + p];
        for (int s = 0; s <= t; ++s)
            acc = fmaf(Wts[t * XS_STRIDE + s], xs[s * XS_STRIDE + p], acc);
        y[(size_t)(seq * LSEQ + t) * D_INNER + h * HEADDIM + p] = acc;
    }
}

// ---------------------------------------------------------------------------
// Gated RMSNorm: y = rmsnorm(y * silu(z)) * norm_w, one block per token
// ---------------------------------------------------------------------------
__global__ __launch_bounds__(256)
void gate_norm_kernel(const float* __restrict__ zx, const float* __restrict__ norm_w,
                      float* __restrict__ y)
{
    const int row = blockIdx.x;
    const int tid = threadIdx.x;
    __shared__ float red[256];

    float vals[4];
    float ss = 0.f;
#pragma unroll
    for (int i = 0; i < 4; ++i) {
        int c = tid + i * 256;
        float z = zx[(size_t)row * D_IN_PROJ + c];
        float g = y[(size_t)row * D_INNER + c] * (z / (1.f + expf(-z)));
        vals[i] = g;
        ss += g * g;
    }
    red[tid] = ss;
    __syncthreads();
    for (int off = 128; off > 0; off >>= 1) {
        if (tid < off) red[tid] += red[tid + off];
        __syncthreads();
    }
    float scale = rsqrtf(red[0] / (float)D_INNER + EPS);
#pragma unroll
    for (int i = 0; i < 4; ++i) {
        int c = tid + i * 256;
        y[(size_t)row * D_INNER + c] = vals[i] * scale * norm_w[c];
    }
}

// ---------------------------------------------------------------------------
// Transpose x (B,H,W,C) -> xv rows in (b*W + w)*H + h order
// ---------------------------------------------------------------------------
__global__ void transpose_v_kernel(const float* __restrict__ x, float* __restrict__ xv)
{
    size_t idx = (size_t)blockIdx.x * blockDim.x + threadIdx.x;
    if (idx >= (size_t)NTOK * D_MODEL) return;
    int rv = (int)(idx >> 9);          // /512
    int c  = (int)(idx & 511);
    int b  = rv >> 12;                 // /4096
    int w  = (rv >> 6) & 63;
    int hh = rv & 63;
    xv[idx] = x[(((size_t)(b * 64 + hh) * 64 + w) << 9) + c];
}

// ---------------------------------------------------------------------------
// Build cat = [v1 (re-transposed) | h1] in output-token order
// ---------------------------------------------------------------------------
__global__ void cat_kernel(const float* __restrict__ vout, const float* __restrict__ hout,
                           float* __restrict__ cat)
{
    size_t idx = (size_t)blockIdx.x * blockDim.x + threadIdx.x;
    if (idx >= (size_t)NTOK * D_INNER) return;
    int r = (int)(idx >> 10);
    int j = (int)(idx & 1023);
    float v;
    if (j < 512) {
        int b = r >> 12, hh = (r >> 6) & 63, w = r & 63;
        int vrow = (b << 12) + (w << 6) + hh;
        v = vout[((size_t)vrow << 9) + j];
    } else {
        v = hout[((size_t)r << 9) + (j - 512)];
    }
    cat[idx] = v;
}

// ---------------------------------------------------------------------------
// Pre-sum fc weights: out = [v1|v1|h1|h1] @ fc_w.T  ==  [v1|h1] @ fceff.T
// ---------------------------------------------------------------------------
__global__ void fceff_kernel(const float* __restrict__ fc_w, float* __restrict__ eff)
{
    int idx = blockIdx.x * blockDim.x + threadIdx.x;
    if (idx >= D_MODEL * D_INNER) return;
    int o = idx >> 10;
    int j = idx & 1023;
    float v;
    if (j < 512) v = fc_w[(size_t)o * 2048 + j] + fc_w[(size_t)o * 2048 + 512 + j];
    else {
        int jj = j - 512;
        v = fc_w[(size_t)o * 2048 + 1024 + jj] + fc_w[(size_t)o * 2048 + 1536 + jj];
    }
    eff[idx] = v;
}

// ---------------------------------------------------------------------------
// Host side
// ---------------------------------------------------------------------------
static void run_direction(const float* u, const float* in_w, const float* conv_w,
                          const float* conv_b, const float* A_log, const float* dt_bias,
                          const float* Dp, const float* norm_w, const float* out_w,
                          float* zx, float* xbc, float* y, float* dirout)
{
    dim3 g1((D_IN_PROJ + 127) / 128, NTOK / 128);
    sgemm_nt_kernel<<<g1, 256>>>(u, in_w, zx, NTOK, D_IN_PROJ, D_MODEL, nullptr);
    conv_silu_kernel<<<(NSEQ * CONV_DIM + 255) / 256, 256>>>(zx, conv_w, conv_b, xbc);
    ssm_kernel<<<NSEQ * NHEADS, 256, SSM_SMEM_BYTES>>>(zx, xbc, A_log, dt_bias, Dp, y);
    gate_norm_kernel<<<NTOK, 256>>>(zx, norm_w, y);
    dim3 g2(D_MODEL / 128, NTOK / 128);
    sgemm_nt_kernel<<<g2, 256>>>(y, out_w, dirout, NTOK, D_MODEL, D_INNER, nullptr);
}

extern "C" void kernel_launch(void* const* d_in, const int* in_sizes, int n_in,
                              void* d_out, int out_size)
{
    (void)in_sizes; (void)n_in; (void)out_size;
    const float* x        = (const float*)d_in[0];
    const float* h_in_w   = (const float*)d_in[1];
    const float* h_conv_w = (const float*)d_in[2];
    const float* h_conv_b = (const float*)d_in[3];
    const float* h_A_log  = (const float*)d_in[4];
    const float* h_dt_b   = (const float*)d_in[5];
    const float* h_D      = (const float*)d_in[6];
    const float* h_norm_w = (const float*)d_in[7];
    const float* h_out_w  = (const float*)d_in[8];
    const float* v_in_w   = (const float*)d_in[9];
    const float* v_conv_w = (const float*)d_in[10];
    const float* v_conv_b = (const float*)d_in[11];
    const float* v_A_log  = (const float*)d_in[12];
    const float* v_dt_b   = (const float*)d_in[13];
    const float* v_D      = (const float*)d_in[14];
    const float* v_norm_w = (const float*)d_in[15];
    const float* v_out_w  = (const float*)d_in[16];
    const float* fc_w     = (const float*)d_in[17];
    const float* fc_b     = (const float*)d_in[18];
    float* out = (float*)d_out;

    float *zx, *xbc, *y, *xv, *hout, *vout, *cat, *fceff;
    cudaGetSymbolAddress((void**)&zx,    g_zx);
    cudaGetSymbolAddress((void**)&xbc,   g_xbc);
    cudaGetSymbolAddress((void**)&y,     g_y);
    cudaGetSymbolAddress((void**)&xv,    g_xv);
    cudaGetSymbolAddress((void**)&hout,  g_hout);
    cudaGetSymbolAddress((void**)&vout,  g_vout);
    cudaGetSymbolAddress((void**)&cat,   g_cat);
    cudaGetSymbolAddress((void**)&fceff, g_fceff);

    cudaFuncSetAttribute(ssm_kernel, cudaFuncAttributeMaxDynamicSharedMemorySize,
                         SSM_SMEM_BYTES);

    // fc effective weights
    fceff_kernel<<<(D_MODEL * D_INNER + 255) / 256, 256>>>(fc_w, fceff);

    // h-direction (u = x directly: rows are already (b*H+h)*W + w)
    run_direction(x, h_in_w, h_conv_w, h_conv_b, h_A_log, h_dt_b, h_D, h_norm_w,
                  h_out_w, zx, xbc, y, hout);

    // v-direction (transposed token order)
    transpose_v_kernel<<<(NTOK * D_MODEL + 255) / 256, 256>>>(x, xv);
    run_direction(xv, v_in_w, v_conv_w, v_conv_b, v_A_log, v_dt_b, v_D, v_norm_w,
                  v_out_w, zx, xbc, y, vout);

    // concat (h2==h1, v2==v1 since the reference flips the batch axis only)
    cat_kernel<<<((size_t)NTOK * D_INNER + 255) / 256, 256>>>(vout, hout, cat);

    // final fc with pre-summed weights + bias
    dim3 g3(D_MODEL / 128, NTOK / 128);
    sgemm_nt_kernel<<<g3, 256>>>(cat, fceff, out, NTOK, D_MODEL, D_INNER, fc_b);
}

// round 3
// speedup vs baseline: 2.3225x; 2.3225x over previous
#include <cuda_runtime.h>
#include <cuda_bf16.h>
#include <math.h>
#include <stdint.h>

// ---------------------------------------------------------------------------
// Problem constants
// ---------------------------------------------------------------------------
#define D_MODEL   512
#define D_STATE   128
#define HEADDIM   64
#define D_INNER   1024
#define NHEADS    16
#define CONV_DIM  1280
#define D_IN_PROJ 2320
#define LSEQ      64
#define NSEQ      128
#define NTOK      8192
#define EPS       1e-5f

#define NPAD_IN   2432            // D_IN_PROJ padded to multiple of 128

// ---------------------------------------------------------------------------
// Device scratch
// ---------------------------------------------------------------------------
__device__ float g_zx   [(size_t)NTOK * D_IN_PROJ];
__device__ float g_xbc  [(size_t)NTOK * CONV_DIM];
__device__ float g_y    [(size_t)NTOK * D_INNER];
__device__ float g_hout [(size_t)NTOK * D_MODEL];
__device__ float g_vout [(size_t)NTOK * D_MODEL];
__device__ float g_fceff[(size_t)D_MODEL * D_INNER];
__device__ __nv_bfloat16 g_asplit[(size_t)NTOK * 3 * D_INNER];    // 8192 x 3072
__device__ __nv_bfloat16 g_wsplit[(size_t)NPAD_IN * 3 * D_MODEL]; // 2432 x 1536

// ---------------------------------------------------------------------------
// Helpers
// ---------------------------------------------------------------------------
__device__ __forceinline__ uint32_t smem_u32(const void* p) {
    uint32_t a;
    asm("{ .reg .u64 t; cvta.to.shared.u64 t, %1; cvt.u32.u64 %0, t; }"
        : "=r"(a) : "l"(p));
    return a;
}
#define SWZ128(o) ((o) ^ (((o) >> 3) & 0x70))
#define CP_ASYNC16(dst, src) \
    asm volatile("cp.async.cg.shared.global [%0], [%1], 16;" :: "r"(dst), "l"(src) : "memory")

__device__ __forceinline__ void ldmatrix_x4(uint32_t* r, uint32_t addr) {
    asm volatile("ldmatrix.sync.aligned.m8n8.x4.shared.b16 {%0,%1,%2,%3}, [%4];"
                 : "=r"(r[0]), "=r"(r[1]), "=r"(r[2]), "=r"(r[3]) : "r"(addr));
}
__device__ __forceinline__ void mma_bf16(float* d, const uint32_t* a,
                                         uint32_t b0, uint32_t b1) {
    asm volatile(
        "mma.sync.aligned.m16n8k16.row.col.f32.bf16.bf16.f32 "
        "{%0,%1,%2,%3}, {%4,%5,%6,%7}, {%8,%9}, {%0,%1,%2,%3};"
        : "+f"(d[0]), "+f"(d[1]), "+f"(d[2]), "+f"(d[3])
        : "r"(a[0]), "r"(a[1]), "r"(a[2]), "r"(a[3]), "r"(b0), "r"(b1));
}

// ---------------------------------------------------------------------------
// mma.sync split-bf16 GEMM: C[m][n] = sum_j A'[m][j] * W'[n][j]  (+ bias)
// Tile 128x128x64(bf16), 256 threads (8 warps, 2x4), double-buffered cp.async.
// SMEM rows are 128 bytes, SW128 swizzled, loaded via ldmatrix.x4 (TN layout).
// ---------------------------------------------------------------------------
#define GSM_A0 0
#define GSM_A1 16384
#define GSM_B0 32768
#define GSM_B1 49152
#define GSM_TOTAL 65536

__device__ __forceinline__ void gemm_load_tile(
    const __nv_bfloat16* __restrict__ A, const __nv_bfloat16* __restrict__ W,
    uint32_t sb, int m0, int n0, int K3, int kt, int buf, int tid)
{
    uint32_t a_dst = sb + (buf ? GSM_A1 : GSM_A0);
    uint32_t b_dst = sb + (buf ? GSM_B1 : GSM_B0);
#pragma unroll
    for (int j = 0; j < 4; ++j) {
        int idx = tid + j * 256;
        int row = idx >> 3, c = idx & 7;
        CP_ASYNC16(a_dst + SWZ128((uint32_t)(row * 128 + c * 16)),
                   A + ((size_t)(m0 + row) * K3 + kt * 64 + c * 8));
    }
#pragma unroll
    for (int j = 0; j < 4; ++j) {
        int idx = tid + j * 256;
        int row = idx >> 3, c = idx & 7;
        CP_ASYNC16(b_dst + SWZ128((uint32_t)(row * 128 + c * 16)),
                   W + ((size_t)(n0 + row) * K3 + kt * 64 + c * 8));
    }
}

__global__ __launch_bounds__(256)
void gemm_tc_kernel(const __nv_bfloat16* __restrict__ A,
                    const __nv_bfloat16* __restrict__ W,
                    float* __restrict__ C,
                    int K3, int N, const float* __restrict__ bias)
{
    extern __shared__ char smem[];
    uint32_t sb = smem_u32(smem);
    const int tid  = threadIdx.x;
    const int wid  = tid >> 5;
    const int lane = tid & 31;
    const int wm   = wid & 1;          // 0..1 : 64-row slab
    const int wn   = wid >> 1;         // 0..3 : 32-col slab
    const int m0   = blockIdx.y * 128;
    const int n0   = blockIdx.x * 128;

    float acc[4][4][4];
#pragma unroll
    for (int i = 0; i < 4; ++i)
#pragma unroll
        for (int j = 0; j < 4; ++j) {
            acc[i][j][0] = 0.f; acc[i][j][1] = 0.f;
            acc[i][j][2] = 0.f; acc[i][j][3] = 0.f;
        }

    const int nK = K3 / 64;
    gemm_load_tile(A, W, sb, m0, n0, K3, 0, 0, tid);
    asm volatile("cp.async.commit_group;" ::: "memory");

    // per-lane ldmatrix row components (constant across k)
    const int lrow = lane & 15;         // row within 16-row tile
    const int lcol = (lane >> 4) * 16;  // 0 or 16 bytes (k half)

    for (int i = 0; i < nK; ++i) {
        if (i + 1 < nK) {
            gemm_load_tile(A, W, sb, m0, n0, K3, i + 1, (i + 1) & 1, tid);
            asm volatile("cp.async.commit_group;" ::: "memory");
            asm volatile("cp.async.wait_group 1;" ::: "memory");
        } else {
            asm volatile("cp.async.wait_group 0;" ::: "memory");
        }
        __syncthreads();

        uint32_t aBase = sb + ((i & 1) ? GSM_A1 : GSM_A0);
        uint32_t bBase = sb + ((i & 1) ? GSM_B1 : GSM_B0);
#pragma unroll
        for (int ks = 0; ks < 4; ++ks) {
            uint32_t af[4][4];
#pragma unroll
            for (int im = 0; im < 4; ++im)
                ldmatrix_x4(af[im], aBase + SWZ128((uint32_t)(
                    (wm * 64 + im * 16 + lrow) * 128 + ks * 32 + lcol)));
            uint32_t bf[2][4];
#pragma unroll
            for (int in2 = 0; in2 < 2; ++in2)
                ldmatrix_x4(bf[in2], bBase + SWZ128((uint32_t)(
                    (wn * 32 + in2 * 16 + lrow) * 128 + ks * 32 + lcol)));
#pragma unroll
            for (int im = 0; im < 4; ++im)
#pragma unroll
                for (int in = 0; in < 4; ++in) {
                    uint32_t b0 = bf[in >> 1][in & 1];
                    uint32_t b1 = bf[in >> 1][2 + (in & 1)];
                    mma_bf16(acc[im][in], af[im], b0, b1);
                }
        }
        __syncthreads();
    }

    // epilogue: d0,d1 -> (row = lane>>2, col = (lane&3)*2, +1); d2,d3 -> row+8
#pragma unroll
    for (int im = 0; im < 4; ++im) {
        int m = m0 + wm * 64 + im * 16 + (lane >> 2);
#pragma unroll
        for (int in = 0; in < 4; ++in) {
            int n = n0 + wn * 32 + in * 8 + (lane & 3) * 2;
            if (n < N) {
                float2 v0 = make_float2(acc[im][in][0], acc[im][in][1]);
                float2 v1 = make_float2(acc[im][in][2], acc[im][in][3]);
                if (bias) {
                    float b0 = bias[n], b1 = bias[n + 1];
                    v0.x += b0; v0.y += b1;
                    v1.x += b0; v1.y += b1;
                }
                *(float2*)(C + (size_t)m * N + n)       = v0;
                *(float2*)(C + (size_t)(m + 8) * N + n) = v1;
            }
        }
    }
}

// ---------------------------------------------------------------------------
// split helpers: fp32 -> [hi | lo | hi] (activations) / [hi | hi | lo] (weights)
// ---------------------------------------------------------------------------
__device__ __forceinline__ void split2(float a, __nv_bfloat16& hi, __nv_bfloat16& lo) {
    hi = __float2bfloat16(a);
    lo = __float2bfloat16(a - __bfloat162float(hi));
}

__global__ void split_act_h_kernel(const float* __restrict__ A, __nv_bfloat16* __restrict__ out)
{
    size_t idx = (size_t)blockIdx.x * blockDim.x + threadIdx.x;
    if (idx >= (size_t)NTOK * 512) return;
    int m = (int)(idx >> 9), k = (int)(idx & 511);
    __nv_bfloat16 hi, lo; split2(A[idx], hi, lo);
    size_t base = (size_t)m * 1536 + k;
    out[base] = hi; out[base + 512] = lo; out[base + 1024] = hi;
}

__global__ void split_act_v_kernel(const float* __restrict__ x, __nv_bfloat16* __restrict__ out)
{
    size_t idx = (size_t)blockIdx.x * blockDim.x + threadIdx.x;
    if (idx >= (size_t)NTOK * 512) return;
    int rv = (int)(idx >> 9), k = (int)(idx & 511);
    int b = rv >> 12, w = (rv >> 6) & 63, hh = rv & 63;
    float a = x[(((size_t)(b * 64 + hh) * 64 + w) << 9) + k];
    __nv_bfloat16 hi, lo; split2(a, hi, lo);
    size_t base = (size_t)rv * 1536 + k;
    out[base] = hi; out[base + 512] = lo; out[base + 1024] = hi;
}

__global__ void split_w_kernel(const float* __restrict__ W, __nv_bfloat16* __restrict__ out,
                               int N, int Npad, int K)
{
    size_t idx = (size_t)blockIdx.x * blockDim.x + threadIdx.x;
    if (idx >= (size_t)Npad * K) return;
    int n = (int)(idx / K), k = (int)(idx - (size_t)n * K);
    float w = (n < N) ? W[(size_t)n * K + k] : 0.f;
    __nv_bfloat16 hi, lo; split2(w, hi, lo);
    size_t base = (size_t)n * 3 * K + k;
    out[base] = hi; out[base + K] = hi; out[base + 2 * K] = lo;
}

// ---------------------------------------------------------------------------
// Depthwise causal conv (width 4) + SiLU
// ---------------------------------------------------------------------------
__global__ void conv_silu_kernel(const float* __restrict__ zx,
                                 const float* __restrict__ cw,
                                 const float* __restrict__ cb,
                                 float* __restrict__ xbc)
{
    int idx = blockIdx.x * blockDim.x + threadIdx.x;
    if (idx >= NSEQ * CONV_DIM) return;
    int seq = idx / CONV_DIM;
    int c   = idx - seq * CONV_DIM;
    float w0 = cw[c * 4 + 0], w1 = cw[c * 4 + 1];
    float w2 = cw[c * 4 + 2], w3 = cw[c * 4 + 3];
    float b  = cb[c];
    size_t ibase = (size_t)seq * LSEQ * D_IN_PROJ + D_INNER + c;
    size_t obase = (size_t)seq * LSEQ * CONV_DIM + c;
    float x0 = 0.f, x1 = 0.f, x2 = 0.f;
    for (int t = 0; t < LSEQ; ++t) {
        float xt = zx[ibase + (size_t)t * D_IN_PROJ];
        float v  = x0 * w0 + x1 * w1 + x2 * w2 + xt * w3 + b;
        xbc[obase + (size_t)t * CONV_DIM] = v / (1.f + expf(-v));
        x0 = x1; x1 = x2; x2 = xt;
    }
}

// ---------------------------------------------------------------------------
// SSM kernel: register-tiled 4x4 per thread, float4 smem loads.
// ---------------------------------------------------------------------------
#define BCS 132
#define XSS 68
#define SSM_SMEM_FLOATS (2 * 64 * BCS + 2 * 64 * XSS + 128)
#define SSM_SMEM_BYTES  (SSM_SMEM_FLOATS * 4)

__global__ __launch_bounds__(256)
void ssm_kernel(const float* __restrict__ zx, const float* __restrict__ xbc,
                const float* __restrict__ A_log, const float* __restrict__ dt_bias,
                const float* __restrict__ Dp, float* __restrict__ y)
{
    extern __shared__ float sm[];
    float* Bs  = sm;
    float* Cs  = Bs + 64 * BCS;
    float* xs  = Cs + 64 * BCS;
    float* Wts = xs + 64 * XSS;
    float* dts = Wts + 64 * XSS;
    float* css = dts + 64;

    const int seq = blockIdx.x >> 4;
    const int h   = blockIdx.x & 15;
    const int tid = threadIdx.x;

    for (int i = tid; i < 64 * 128; i += 256) {
        int t = i >> 7, n = i & 127;
        size_t base = (size_t)(seq * LSEQ + t) * CONV_DIM;
        Bs[t * BCS + n] = xbc[base + D_INNER + n];
        Cs[t * BCS + n] = xbc[base + D_INNER + D_STATE + n];
    }
    for (int i = tid; i < 64 * 64; i += 256) {
        int t = i >> 6, p = i & 63;
        xs[t * XSS + p] = xbc[(size_t)(seq * LSEQ + t) * CONV_DIM + h * HEADDIM + p];
    }
    if (tid < 64) {
        float raw = zx[(size_t)(seq * LSEQ + tid) * D_IN_PROJ + (D_INNER + CONV_DIM) + h]
                    + dt_bias[h];
        dts[tid] = (raw > 20.f) ? raw : log1pf(expf(raw));
    }
    __syncthreads();
    if (tid == 0) {
        float a = -expf(A_log[h]);
        float run = 0.f;
        for (int t = 0; t < 64; ++t) { run += dts[t] * a; css[t] = run; }
    }
    __syncthreads();

    const int tt = (tid >> 4) << 2;     // t tile base
    const int ss = (tid & 15) << 2;     // s / p tile base

    // Phase 1: W[t][s] 4x4 tile
    float wa[4][4];
#pragma unroll
    for (int i = 0; i < 4; ++i)
#pragma unroll
        for (int j = 0; j < 4; ++j) wa[i][j] = 0.f;

    if (ss <= tt + 3) {
        for (int n = 0; n < 128; n += 4) {
            float4 cr[4], br[4];
#pragma unroll
            for (int i = 0; i < 4; ++i) cr[i] = *(const float4*)&Cs[(tt + i) * BCS + n];
#pragma unroll
            for (int j = 0; j < 4; ++j) br[j] = *(const float4*)&Bs[(ss + j) * BCS + n];
#pragma unroll
            for (int i = 0; i < 4; ++i)
#pragma unroll
                for (int j = 0; j < 4; ++j) {
                    wa[i][j] = fmaf(cr[i].x, br[j].x, wa[i][j]);
                    wa[i][j] = fmaf(cr[i].y, br[j].y, wa[i][j]);
                    wa[i][j] = fmaf(cr[i].z, br[j].z, wa[i][j]);
                    wa[i][j] = fmaf(cr[i].w, br[j].w, wa[i][j]);
                }
        }
    }
#pragma unroll
    for (int i = 0; i < 4; ++i)
#pragma unroll
        for (int j = 0; j < 4; ++j) {
            int t = tt + i, s = ss + j;
            float v = (s <= t) ? wa[i][j] * expf(css[t] - css[s]) * dts[s] : 0.f;
            Wts[t * XSS + s] = v;
        }
    __syncthreads();

    // Phase 2: y[t][p] 4x4 tile (pp = ss)
    const float dcoef = Dp[h];
    float ya[4][4];
#pragma unroll
    for (int i = 0; i < 4; ++i) {
        float4 xv = *(const float4*)&xs[(tt + i) * XSS + ss];
        ya[i][0] = dcoef * xv.x; ya[i][1] = dcoef * xv.y;
        ya[i][2] = dcoef * xv.z; ya[i][3] = dcoef * xv.w;
    }
    for (int s0 = 0; s0 <= tt + 3; s0 += 4) {
        float4 wr[4], xr[4];
#pragma unroll
        for (int i = 0; i < 4; ++i) wr[i] = *(const float4*)&Wts[(tt + i) * XSS + s0];
#pragma unroll
        for (int k = 0; k < 4; ++k) xr[k] = *(const float4*)&xs[(s0 + k) * XSS + ss];
#pragma unroll
        for (int i = 0; i < 4; ++i) {
            ya[i][0] = fmaf(wr[i].x, xr[0].x, ya[i][0]);
            ya[i][1] = fmaf(wr[i].x, xr[0].y, ya[i][1]);
            ya[i][2] = fmaf(wr[i].x, xr[0].z, ya[i][2]);
            ya[i][3] = fmaf(wr[i].x, xr[0].w, ya[i][3]);
            ya[i][0] = fmaf(wr[i].y, xr[1].x, ya[i][0]);
            ya[i][1] = fmaf(wr[i].y, xr[1].y, ya[i][1]);
            ya[i][2] = fmaf(wr[i].y, xr[1].z, ya[i][2]);
            ya[i][3] = fmaf(wr[i].y, xr[1].w, ya[i][3]);
            ya[i][0] = fmaf(wr[i].z, xr[2].x, ya[i][0]);
            ya[i][1] = fmaf(wr[i].z, xr[2].y, ya[i][1]);
            ya[i][2] = fmaf(wr[i].z, xr[2].z, ya[i][2]);
            ya[i][3] = fmaf(wr[i].z, xr[2].w, ya[i][3]);
            ya[i][0] = fmaf(wr[i].w, xr[3].x, ya[i][0]);
            ya[i][1] = fmaf(wr[i].w, xr[3].y, ya[i][1]);
            ya[i][2] = fmaf(wr[i].w, xr[3].z, ya[i][2]);
            ya[i][3] = fmaf(wr[i].w, xr[3].w, ya[i][3]);
        }
    }
#pragma unroll
    for (int i = 0; i < 4; ++i) {
        float4 v = make_float4(ya[i][0], ya[i][1], ya[i][2], ya[i][3]);
        *(float4*)&y[(size_t)(seq * LSEQ + tt + i) * D_INNER + h * HEADDIM + ss] = v;
    }
}

// ---------------------------------------------------------------------------
// Gated RMSNorm fused with split emit
// ---------------------------------------------------------------------------
__global__ __launch_bounds__(256)
void gate_norm_split_kernel(const float* __restrict__ zx, const float* __restrict__ norm_w,
                            const float* __restrict__ y, __nv_bfloat16* __restrict__ out)
{
    const int row = blockIdx.x;
    const int tid = threadIdx.x;
    __shared__ float red[256];

    float vals[4];
    float ss = 0.f;
#pragma unroll
    for (int i = 0; i < 4; ++i) {
        int c = tid + i * 256;
        float z = zx[(size_t)row * D_IN_PROJ + c];
        float g = y[(size_t)row * D_INNER + c] * (z / (1.f + expf(-z)));
        vals[i] = g;
        ss += g * g;
    }
    red[tid] = ss;
    __syncthreads();
    for (int off = 128; off > 0; off >>= 1) {
        if (tid < off) red[tid] += red[tid + off];
        __syncthreads();
    }
    float scale = rsqrtf(red[0] / (float)D_INNER + EPS);
#pragma unroll
    for (int i = 0; i < 4; ++i) {
        int c = tid + i * 256;
        float g = vals[i] * scale * norm_w[c];
        __nv_bfloat16 hi, lo; split2(g, hi, lo);
        size_t base = (size_t)row * 3072 + c;
        out[base] = hi; out[base + 1024] = lo; out[base + 2048] = hi;
    }
}

// ---------------------------------------------------------------------------
// cat = [v1 (re-transposed) | h1] fused with split emit
// ---------------------------------------------------------------------------
__global__ void cat_split_kernel(const float* __restrict__ vout, const float* __restrict__ hout,
                                 __nv_bfloat16* __restrict__ out)
{
    size_t idx = (size_t)blockIdx.x * blockDim.x + threadIdx.x;
    if (idx >= (size_t)NTOK * D_INNER) return;
    int r = (int)(idx >> 10);
    int j = (int)(idx & 1023);
    float v;
    if (j < 512) {
        int b = r >> 12, hh = (r >> 6) & 63, w = r & 63;
        int vrow = (b << 12) + (w << 6) + hh;
        v = vout[((size_t)vrow << 9) + j];
    } else {
        v = hout[((size_t)r << 9) + (j - 512)];
    }
    __nv_bfloat16 hi, lo; split2(v, hi, lo);
    size_t base = (size_t)r * 3072 + j;
    out[base] = hi; out[base + 1024] = lo; out[base + 2048] = hi;
}

__global__ void fceff_kernel(const float* __restrict__ fc_w, float* __restrict__ eff)
{
    int idx = blockIdx.x * blockDim.x + threadIdx.x;
    if (idx >= D_MODEL * D_INNER) return;
    int o = idx >> 10;
    int j = idx & 1023;
    float v;
    if (j < 512) v = fc_w[(size_t)o * 2048 + j] + fc_w[(size_t)o * 2048 + 512 + j];
    else {
        int jj = j - 512;
        v = fc_w[(size_t)o * 2048 + 1024 + jj] + fc_w[(size_t)o * 2048 + 1536 + jj];
    }
    eff[idx] = v;
}

// ---------------------------------------------------------------------------
// Host side
// ---------------------------------------------------------------------------
extern "C" void kernel_launch(void* const* d_in, const int* in_sizes, int n_in,
                              void* d_out, int out_size)
{
    (void)in_sizes; (void)n_in; (void)out_size;
    const float* x        = (const float*)d_in[0];
    const float* h_in_w   = (const float*)d_in[1];
    const float* h_conv_w = (const float*)d_in[2];
    const float* h_conv_b = (const float*)d_in[3];
    const float* h_A_log  = (const float*)d_in[4];
    const float* h_dt_b   = (const float*)d_in[5];
    const float* h_D      = (const float*)d_in[6];
    const float* h_norm_w = (const float*)d_in[7];
    const float* h_out_w  = (const float*)d_in[8];
    const float* v_in_w   = (const float*)d_in[9];
    const float* v_conv_w = (const float*)d_in[10];
    const float* v_conv_b = (const float*)d_in[11];
    const float* v_A_log  = (const float*)d_in[12];
    const float* v_dt_b   = (const float*)d_in[13];
    const float* v_D      = (const float*)d_in[14];
    const float* v_norm_w = (const float*)d_in[15];
    const float* v_out_w  = (const float*)d_in[16];
    const float* fc_w     = (const float*)d_in[17];
    const float* fc_b     = (const float*)d_in[18];
    float* out = (float*)d_out;

    float *zx, *xbc, *y, *hout, *vout, *fceff;
    __nv_bfloat16 *asplit, *wsplit;
    cudaGetSymbolAddress((void**)&zx,     g_zx);
    cudaGetSymbolAddress((void**)&xbc,    g_xbc);
    cudaGetSymbolAddress((void**)&y,      g_y);
    cudaGetSymbolAddress((void**)&hout,   g_hout);
    cudaGetSymbolAddress((void**)&vout,   g_vout);
    cudaGetSymbolAddress((void**)&fceff,  g_fceff);
    cudaGetSymbolAddress((void**)&asplit, g_asplit);
    cudaGetSymbolAddress((void**)&wsplit, g_wsplit);

    cudaFuncSetAttribute(ssm_kernel, cudaFuncAttributeMaxDynamicSharedMemorySize,
                         SSM_SMEM_BYTES);
    cudaFuncSetAttribute(gemm_tc_kernel, cudaFuncAttributeMaxDynamicSharedMemorySize,
                         GSM_TOTAL);

    const int TPB = 256;
    for (int dir = 0; dir < 2; ++dir) {
        const float* in_w   = dir ? v_in_w   : h_in_w;
        const float* conv_w = dir ? v_conv_w : h_conv_w;
        const float* conv_b = dir ? v_conv_b : h_conv_b;
        const float* A_log  = dir ? v_A_log  : h_A_log;
        const float* dt_b   = dir ? v_dt_b   : h_dt_b;
        const float* Dp     = dir ? v_D      : h_D;
        const float* norm_w = dir ? v_norm_w : h_norm_w;
        const float* out_w  = dir ? v_out_w  : h_out_w;
        float* dirout       = dir ? vout     : hout;

        // in-proj: split + mma GEMM (K3=1536, N=2320 padded 2432)
        if (dir == 0)
            split_act_h_kernel<<<(NTOK * 512 + TPB - 1) / TPB, TPB>>>(x, asplit);
        else
            split_act_v_kernel<<<(NTOK * 512 + TPB - 1) / TPB, TPB>>>(x, asplit);
        split_w_kernel<<<(NPAD_IN * 512 + TPB - 1) / TPB, TPB>>>(in_w, wsplit,
                                                                 D_IN_PROJ, NPAD_IN, 512);
        {
            dim3 g(NPAD_IN / 128, NTOK / 128);
            gemm_tc_kernel<<<g, 256, GSM_TOTAL>>>(asplit, wsplit, zx, 1536, D_IN_PROJ, nullptr);
        }

        conv_silu_kernel<<<(NSEQ * CONV_DIM + TPB - 1) / TPB, TPB>>>(zx, conv_w, conv_b, xbc);
        ssm_kernel<<<NSEQ * NHEADS, 256, SSM_SMEM_BYTES>>>(zx, xbc, A_log, dt_b, Dp, y);
        gate_norm_split_kernel<<<NTOK, 256>>>(zx, norm_w, y, asplit);

        // out-proj: K3=3072, N=512
        split_w_kernel<<<(512 * 1024 + TPB - 1) / TPB, TPB>>>(out_w, wsplit, 512, 512, 1024);
        {
            dim3 g(512 / 128, NTOK / 128);
            gemm_tc_kernel<<<g, 256, GSM_TOTAL>>>(asplit, wsplit, dirout, 3072, 512, nullptr);
        }
    }

    // final fc: cat + split, pre-summed weights, bias
    cat_split_kernel<<<((size_t)NTOK * D_INNER + TPB - 1) / TPB, TPB>>>(vout, hout, asplit);
    fceff_kernel<<<(D_MODEL * D_INNER + TPB - 1) / TPB, TPB>>>(fc_w, fceff);
    split_w_kernel<<<(512 * 1024 + TPB - 1) / TPB, TPB>>>(fceff, wsplit, 512, 512, 1024);
    {
        dim3 g(512 / 128, NTOK / 128);
        gemm_tc_kernel<<<g, 256, GSM_TOTAL>>>(asplit, wsplit, out, 3072, 512, fc_b);
    }
}

// round 4
// speedup vs baseline: 2.6630x; 1.1466x over previous
#include <cuda_runtime.h>
#include <cuda_fp16.h>
#include <cuda_bf16.h>
#include <math.h>
#include <stdint.h>

// ---------------------------------------------------------------------------
// Problem constants
// ---------------------------------------------------------------------------
#define D_MODEL   512
#define D_STATE   128
#define HEADDIM   64
#define D_INNER   1024
#define NHEADS    16
#define CONV_DIM  1280
#define D_IN_PROJ 2320
#define LSEQ      64
#define NSEQ      128
#define NTOK      8192
#define EPS       1e-5f

#define NPAD_IN   2432            // D_IN_PROJ padded to multiple of 128

// ---------------------------------------------------------------------------
// Device scratch
// ---------------------------------------------------------------------------
__device__ float g_zx   [(size_t)NTOK * D_IN_PROJ];
__device__ float g_xbc  [(size_t)NTOK * CONV_DIM];
__device__ float g_y    [(size_t)NTOK * D_INNER];
__device__ float g_hout [(size_t)NTOK * D_MODEL];
__device__ float g_vout [(size_t)NTOK * D_MODEL];
__device__ float g_fceff[(size_t)D_MODEL * D_INNER];
__device__ __half g_asplit[(size_t)NTOK * 2 * D_INNER];    // 8192 x 2048
__device__ __half g_wsplit[(size_t)NPAD_IN * 2 * D_MODEL]; // 2432 x 1024

// ---------------------------------------------------------------------------
// Helpers
// ---------------------------------------------------------------------------
__device__ __forceinline__ uint32_t smem_u32(const void* p) {
    uint32_t a;
    asm("{ .reg .u64 t; cvta.to.shared.u64 t, %1; cvt.u32.u64 %0, t; }"
        : "=r"(a) : "l"(p));
    return a;
}
#define SWZ128(o) ((o) ^ (((o) >> 3) & 0x70))
#define CP_ASYNC16(dst, src) \
    asm volatile("cp.async.cg.shared.global [%0], [%1], 16;" :: "r"(dst), "l"(src) : "memory")

__device__ __forceinline__ void ldmatrix_x4(uint32_t* r, uint32_t addr) {
    asm volatile("ldmatrix.sync.aligned.m8n8.x4.shared.b16 {%0,%1,%2,%3}, [%4];"
                 : "=r"(r[0]), "=r"(r[1]), "=r"(r[2]), "=r"(r[3]) : "r"(addr));
}
__device__ __forceinline__ void mma_f16(float* d, const uint32_t* a,
                                        uint32_t b0, uint32_t b1) {
    asm volatile(
        "mma.sync.aligned.m16n8k16.row.col.f32.f16.f16.f32 "
        "{%0,%1,%2,%3}, {%4,%5,%6,%7}, {%8,%9}, {%0,%1,%2,%3};"
        : "+f"(d[0]), "+f"(d[1]), "+f"(d[2]), "+f"(d[3])
        : "r"(a[0]), "r"(a[1]), "r"(a[2]), "r"(a[3]), "r"(b0), "r"(b1));
}

// ---------------------------------------------------------------------------
// mma.sync split-fp16 GEMM: C[m][n] = sum_j A'[m][j] * W'[n][j]  (+ bias)
// Tile 128x128x64(fp16), 256 threads (8 warps, 2x4), 3-stage cp.async pipe.
// SMEM rows 128 bytes, SW128 swizzled, loaded via ldmatrix.x4 (TN layout).
// ---------------------------------------------------------------------------
#define GST       32768                    // bytes per stage (A 16K + B 16K)
#define GSM_TOTAL (3 * GST)                // 96 KB

__device__ __forceinline__ void gemm_load_tile(
    const __half* __restrict__ A, const __half* __restrict__ W,
    uint32_t sb, int m0, int n0, int K2, int kt, int stage, int tid)
{
    uint32_t a_dst = sb + stage * GST;
    uint32_t b_dst = a_dst + 16384;
#pragma unroll
    for (int j = 0; j < 4; ++j) {
        int idx = tid + j * 256;
        int row = idx >> 3, c = idx & 7;
        CP_ASYNC16(a_dst + SWZ128((uint32_t)(row * 128 + c * 16)),
                   A + ((size_t)(m0 + row) * K2 + kt * 64 + c * 8));
    }
#pragma unroll
    for (int j = 0; j < 4; ++j) {
        int idx = tid + j * 256;
        int row = idx >> 3, c = idx & 7;
        CP_ASYNC16(b_dst + SWZ128((uint32_t)(row * 128 + c * 16)),
                   W + ((size_t)(n0 + row) * K2 + kt * 64 + c * 8));
    }
}

__global__ __launch_bounds__(256)
void gemm_tc_kernel(const __half* __restrict__ A,
                    const __half* __restrict__ W,
                    float* __restrict__ C,
                    int K2, int N, const float* __restrict__ bias)
{
    extern __shared__ char smem[];
    uint32_t sb = smem_u32(smem);
    const int tid  = threadIdx.x;
    const int wid  = tid >> 5;
    const int lane = tid & 31;
    const int wm   = wid & 1;          // 0..1 : 64-row slab
    const int wn   = wid >> 1;         // 0..3 : 32-col slab
    const int m0   = blockIdx.y * 128;
    const int n0   = blockIdx.x * 128;

    float acc[4][4][4];
#pragma unroll
    for (int i = 0; i < 4; ++i)
#pragma unroll
        for (int j = 0; j < 4; ++j) {
            acc[i][j][0] = 0.f; acc[i][j][1] = 0.f;
            acc[i][j][2] = 0.f; acc[i][j][3] = 0.f;
        }

    const int nK = K2 / 64;

    // prologue: stages 0, 1
    gemm_load_tile(A, W, sb, m0, n0, K2, 0, 0, tid);
    asm volatile("cp.async.commit_group;" ::: "memory");
    gemm_load_tile(A, W, sb, m0, n0, K2, 1, 1, tid);
    asm volatile("cp.async.commit_group;" ::: "memory");

    const int lrow = lane & 15;
    const int lcol = (lane >> 4) * 16;

    int stage = 0;
    for (int i = 0; i < nK; ++i) {
        if (i < nK - 1) asm volatile("cp.async.wait_group 1;" ::: "memory");
        else            asm volatile("cp.async.wait_group 0;" ::: "memory");
        __syncthreads();

        if (i + 2 < nK) {
            int s2 = stage + 2; if (s2 >= 3) s2 -= 3;
            gemm_load_tile(A, W, sb, m0, n0, K2, i + 2, s2, tid);
            asm volatile("cp.async.commit_group;" ::: "memory");
        }

        uint32_t aBase = sb + stage * GST;
        uint32_t bBase = aBase + 16384;
#pragma unroll
        for (int ks = 0; ks < 4; ++ks) {
            uint32_t af[4][4];
#pragma unroll
            for (int im = 0; im < 4; ++im)
                ldmatrix_x4(af[im], aBase + SWZ128((uint32_t)(
                    (wm * 64 + im * 16 + lrow) * 128 + ks * 32 + lcol)));
            uint32_t bf[2][4];
#pragma unroll
            for (int in2 = 0; in2 < 2; ++in2)
                ldmatrix_x4(bf[in2], bBase + SWZ128((uint32_t)(
                    (wn * 32 + in2 * 16 + lrow) * 128 + ks * 32 + lcol)));
#pragma unroll
            for (int im = 0; im < 4; ++im)
#pragma unroll
                for (int in = 0; in < 4; ++in) {
                    uint32_t b0 = bf[in >> 1][in & 1];
                    uint32_t b1 = bf[in >> 1][2 + (in & 1)];
                    mma_f16(acc[im][in], af[im], b0, b1);
                }
        }
        if (++stage == 3) stage = 0;
    }

    // epilogue
#pragma unroll
    for (int im = 0; im < 4; ++im) {
        int m = m0 + wm * 64 + im * 16 + (lane >> 2);
#pragma unroll
        for (int in = 0; in < 4; ++in) {
            int n = n0 + wn * 32 + in * 8 + (lane & 3) * 2;
            if (n < N) {
                float2 v0 = make_float2(acc[im][in][0], acc[im][in][1]);
                float2 v1 = make_float2(acc[im][in][2], acc[im][in][3]);
                if (bias) {
                    float b0 = bias[n], b1 = bias[n + 1];
                    v0.x += b0; v0.y += b1;
                    v1.x += b0; v1.y += b1;
                }
                *(float2*)(C + (size_t)m * N + n)       = v0;
                *(float2*)(C + (size_t)(m + 8) * N + n) = v1;
            }
        }
    }
}

// ---------------------------------------------------------------------------
// split helpers: fp32 -> fp16 [hi | lo] (activations) / [wh | wh] (weights)
// ---------------------------------------------------------------------------
__device__ __forceinline__ void split2h(float a, __half& hi, __half& lo) {
    hi = __float2half_rn(a);
    lo = __float2half_rn(a - __half2float(hi));
}

__global__ void split_act_h_kernel(const float* __restrict__ A, __half* __restrict__ out)
{
    size_t idx = (size_t)blockIdx.x * blockDim.x + threadIdx.x;
    if (idx >= (size_t)NTOK * 512) return;
    int m = (int)(idx >> 9), k = (int)(idx & 511);
    __half hi, lo; split2h(A[idx], hi, lo);
    size_t base = (size_t)m * 1024 + k;
    out[base] = hi; out[base + 512] = lo;
}

__global__ void split_act_v_kernel(const float* __restrict__ x, __half* __restrict__ out)
{
    size_t idx = (size_t)blockIdx.x * blockDim.x + threadIdx.x;
    if (idx >= (size_t)NTOK * 512) return;
    int rv = (int)(idx >> 9), k = (int)(idx & 511);
    int b = rv >> 12, w = (rv >> 6) & 63, hh = rv & 63;
    float a = x[(((size_t)(b * 64 + hh) * 64 + w) << 9) + k];
    __half hi, lo; split2h(a, hi, lo);
    size_t base = (size_t)rv * 1024 + k;
    out[base] = hi; out[base + 512] = lo;
}

__global__ void split_w_kernel(const float* __restrict__ W, __half* __restrict__ out,
                               int N, int Npad, int K)
{
    size_t idx = (size_t)blockIdx.x * blockDim.x + threadIdx.x;
    if (idx >= (size_t)Npad * K) return;
    int n = (int)(idx / K), k = (int)(idx - (size_t)n * K);
    float w = (n < N) ? W[(size_t)n * K + k] : 0.f;
    __half wh = __float2half_rn(w);
    size_t base = (size_t)n * 2 * K + k;
    out[base] = wh; out[base + K] = wh;
}

// ---------------------------------------------------------------------------
// Depthwise causal conv (width 4) + SiLU, float4 over 4 channels per thread
// ---------------------------------------------------------------------------
__global__ void conv_silu_kernel(const float* __restrict__ zx,
                                 const float* __restrict__ cw,
                                 const float* __restrict__ cb,
                                 float* __restrict__ xbc)
{
    int idx = blockIdx.x * blockDim.x + threadIdx.x;
    if (idx >= NSEQ * (CONV_DIM / 4)) return;
    int seq = idx / (CONV_DIM / 4);
    int c4  = idx - seq * (CONV_DIM / 4);
    int c   = c4 * 4;

    float4 w[4];
#pragma unroll
    for (int j = 0; j < 4; ++j) w[j] = *(const float4*)(cw + (c + j) * 4);
    float4 b = *(const float4*)(cb + c);

    size_t ibase = (size_t)seq * LSEQ * D_IN_PROJ + D_INNER + c;
    size_t obase = (size_t)seq * LSEQ * CONV_DIM + c;

    float4 x0 = make_float4(0.f, 0.f, 0.f, 0.f);
    float4 x1 = x0, x2 = x0;
    for (int t = 0; t < LSEQ; ++t) {
        float4 xt = *(const float4*)(zx + ibase + (size_t)t * D_IN_PROJ);
        float4 v;
        v.x = fmaf(x0.x, w[0].x, fmaf(x1.x, w[0].y, fmaf(x2.x, w[0].z, fmaf(xt.x, w[0].w, b.x))));
        v.y = fmaf(x0.y, w[1].x, fmaf(x1.y, w[1].y, fmaf(x2.y, w[1].z, fmaf(xt.y, w[1].w, b.y))));
        v.z = fmaf(x0.z, w[2].x, fmaf(x1.z, w[2].y, fmaf(x2.z, w[2].z, fmaf(xt.z, w[2].w, b.z))));
        v.w = fmaf(x0.w, w[3].x, fmaf(x1.w, w[3].y, fmaf(x2.w, w[3].z, fmaf(xt.w, w[3].w, b.w))));
        v.x = v.x / (1.f + expf(-v.x));
        v.y = v.y / (1.f + expf(-v.y));
        v.z = v.z / (1.f + expf(-v.z));
        v.w = v.w / (1.f + expf(-v.w));
        *(float4*)(xbc + obase + (size_t)t * CONV_DIM) = v;
        x0 = x1; x1 = x2; x2 = xt;
    }
}

// ---------------------------------------------------------------------------
// SSM kernel: register-tiled 4x4 per thread, float4 smem loads.
// ---------------------------------------------------------------------------
#define BCS 132
#define XSS 68
#define SSM_SMEM_FLOATS (2 * 64 * BCS + 2 * 64 * XSS + 128)
#define SSM_SMEM_BYTES  (SSM_SMEM_FLOATS * 4)

__global__ __launch_bounds__(256)
void ssm_kernel(const float* __restrict__ zx, const float* __restrict__ xbc,
                const float* __restrict__ A_log, const float* __restrict__ dt_bias,
                const float* __restrict__ Dp, float* __restrict__ y)
{
    extern __shared__ float sm[];
    float* Bs  = sm;
    float* Cs  = Bs + 64 * BCS;
    float* xs  = Cs + 64 * BCS;
    float* Wts = xs + 64 * XSS;
    float* dts = Wts + 64 * XSS;
    float* css = dts + 64;

    const int seq = blockIdx.x >> 4;
    const int h   = blockIdx.x & 15;
    const int tid = threadIdx.x;

    for (int i = tid; i < 64 * 128; i += 256) {
        int t = i >> 7, n = i & 127;
        size_t base = (size_t)(seq * LSEQ + t) * CONV_DIM;
        Bs[t * BCS + n] = xbc[base + D_INNER + n];
        Cs[t * BCS + n] = xbc[base + D_INNER + D_STATE + n];
    }
    for (int i = tid; i < 64 * 64; i += 256) {
        int t = i >> 6, p = i & 63;
        xs[t * XSS + p] = xbc[(size_t)(seq * LSEQ + t) * CONV_DIM + h * HEADDIM + p];
    }
    if (tid < 64) {
        float raw = zx[(size_t)(seq * LSEQ + tid) * D_IN_PROJ + (D_INNER + CONV_DIM) + h]
                    + dt_bias[h];
        dts[tid] = (raw > 20.f) ? raw : log1pf(expf(raw));
    }
    __syncthreads();
    if (tid == 0) {
        float a = -expf(A_log[h]);
        float run = 0.f;
        for (int t = 0; t < 64; ++t) { run += dts[t] * a; css[t] = run; }
    }
    __syncthreads();

    const int tt = (tid >> 4) << 2;
    const int ss = (tid & 15) << 2;

    float wa[4][4];
#pragma unroll
    for (int i = 0; i < 4; ++i)
#pragma unroll
        for (int j = 0; j < 4; ++j) wa[i][j] = 0.f;

    if (ss <= tt + 3) {
        for (int n = 0; n < 128; n += 4) {
            float4 cr[4], br[4];
#pragma unroll
            for (int i = 0; i < 4; ++i) cr[i] = *(const float4*)&Cs[(tt + i) * BCS + n];
#pragma unroll
            for (int j = 0; j < 4; ++j) br[j] = *(const float4*)&Bs[(ss + j) * BCS + n];
#pragma unroll
            for (int i = 0; i < 4; ++i)
#pragma unroll
                for (int j = 0; j < 4; ++j) {
                    wa[i][j] = fmaf(cr[i].x, br[j].x, wa[i][j]);
                    wa[i][j] = fmaf(cr[i].y, br[j].y, wa[i][j]);
                    wa[i][j] = fmaf(cr[i].z, br[j].z, wa[i][j]);
                    wa[i][j] = fmaf(cr[i].w, br[j].w, wa[i][j]);
                }
        }
    }
#pragma unroll
    for (int i = 0; i < 4; ++i)
#pragma unroll
        for (int j = 0; j < 4; ++j) {
            int t = tt + i, s = ss + j;
            float v = (s <= t) ? wa[i][j] * expf(css[t] - css[s]) * dts[s] : 0.f;
            Wts[t * XSS + s] = v;
        }
    __syncthreads();

    const float dcoef = Dp[h];
    float ya[4][4];
#pragma unroll
    for (int i = 0; i < 4; ++i) {
        float4 xv = *(const float4*)&xs[(tt + i) * XSS + ss];
        ya[i][0] = dcoef * xv.x; ya[i][1] = dcoef * xv.y;
        ya[i][2] = dcoef * xv.z; ya[i][3] = dcoef * xv.w;
    }
    for (int s0 = 0; s0 <= tt + 3; s0 += 4) {
        float4 wr[4], xr[4];
#pragma unroll
        for (int i = 0; i < 4; ++i) wr[i] = *(const float4*)&Wts[(tt + i) * XSS + s0];
#pragma unroll
        for (int k = 0; k < 4; ++k) xr[k] = *(const float4*)&xs[(s0 + k) * XSS + ss];
#pragma unroll
        for (int i = 0; i < 4; ++i) {
            ya[i][0] = fmaf(wr[i].x, xr[0].x, ya[i][0]);
            ya[i][1] = fmaf(wr[i].x, xr[0].y, ya[i][1]);
            ya[i][2] = fmaf(wr[i].x, xr[0].z, ya[i][2]);
            ya[i][3] = fmaf(wr[i].x, xr[0].w, ya[i][3]);
            ya[i][0] = fmaf(wr[i].y, xr[1].x, ya[i][0]);
            ya[i][1] = fmaf(wr[i].y, xr[1].y, ya[i][1]);
            ya[i][2] = fmaf(wr[i].y, xr[1].z, ya[i][2]);
            ya[i][3] = fmaf(wr[i].y, xr[1].w, ya[i][3]);
            ya[i][0] = fmaf(wr[i].z, xr[2].x, ya[i][0]);
            ya[i][1] = fmaf(wr[i].z, xr[2].y, ya[i][1]);
            ya[i][2] = fmaf(wr[i].z, xr[2].z, ya[i][2]);
            ya[i][3] = fmaf(wr[i].z, xr[2].w, ya[i][3]);
            ya[i][0] = fmaf(wr[i].w, xr[3].x, ya[i][0]);
            ya[i][1] = fmaf(wr[i].w, xr[3].y, ya[i][1]);
            ya[i][2] = fmaf(wr[i].w, xr[3].z, ya[i][2]);
            ya[i][3] = fmaf(wr[i].w, xr[3].w, ya[i][3]);
        }
    }
#pragma unroll
    for (int i = 0; i < 4; ++i) {
        float4 v = make_float4(ya[i][0], ya[i][1], ya[i][2], ya[i][3]);
        *(float4*)&y[(size_t)(seq * LSEQ + tt + i) * D_INNER + h * HEADDIM + ss] = v;
    }
}

// ---------------------------------------------------------------------------
// Gated RMSNorm fused with fp16 split emit
// ---------------------------------------------------------------------------
__global__ __launch_bounds__(256)
void gate_norm_split_kernel(const float* __restrict__ zx, const float* __restrict__ norm_w,
                            const float* __restrict__ y, __half* __restrict__ out)
{
    const int row = blockIdx.x;
    const int tid = threadIdx.x;
    __shared__ float red[256];

    float vals[4];
    float ss = 0.f;
#pragma unroll
    for (int i = 0; i < 4; ++i) {
        int c = tid + i * 256;
        float z = zx[(size_t)row * D_IN_PROJ + c];
        float g = y[(size_t)row * D_INNER + c] * (z / (1.f + expf(-z)));
        vals[i] = g;
        ss += g * g;
    }
    red[tid] = ss;
    __syncthreads();
    for (int off = 128; off > 0; off >>= 1) {
        if (tid < off) red[tid] += red[tid + off];
        __syncthreads();
    }
    float scale = rsqrtf(red[0] / (float)D_INNER + EPS);
#pragma unroll
    for (int i = 0; i < 4; ++i) {
        int c = tid + i * 256;
        float g = vals[i] * scale * norm_w[c];
        __half hi, lo; split2h(g, hi, lo);
        size_t base = (size_t)row * 2048 + c;
        out[base] = hi; out[base + 1024] = lo;
    }
}

// ---------------------------------------------------------------------------
// cat = [v1 (re-transposed) | h1] fused with fp16 split emit
// ---------------------------------------------------------------------------
__global__ void cat_split_kernel(const float* __restrict__ vout, const float* __restrict__ hout,
                                 __half* __restrict__ out)
{
    size_t idx = (size_t)blockIdx.x * blockDim.x + threadIdx.x;
    if (idx >= (size_t)NTOK * D_INNER) return;
    int r = (int)(idx >> 10);
    int j = (int)(idx & 1023);
    float v;
    if (j < 512) {
        int b = r >> 12, hh = (r >> 6) & 63, w = r & 63;
        int vrow = (b << 12) + (w << 6) + hh;
        v = vout[((size_t)vrow << 9) + j];
    } else {
        v = hout[((size_t)r << 9) + (j - 512)];
    }
    __half hi, lo; split2h(v, hi, lo);
    size_t base = (size_t)r * 2048 + j;
    out[base] = hi; out[base + 1024] = lo;
}

__global__ void fceff_kernel(const float* __restrict__ fc_w, float* __restrict__ eff)
{
    int idx = blockIdx.x * blockDim.x + threadIdx.x;
    if (idx >= D_MODEL * D_INNER) return;
    int o = idx >> 10;
    int j = idx & 1023;
    float v;
    if (j < 512) v = fc_w[(size_t)o * 2048 + j] + fc_w[(size_t)o * 2048 + 512 + j];
    else {
        int jj = j - 512;
        v = fc_w[(size_t)o * 2048 + 1024 + jj] + fc_w[(size_t)o * 2048 + 1536 + jj];
    }
    eff[idx] = v;
}

// ---------------------------------------------------------------------------
// Host side
// ---------------------------------------------------------------------------
extern "C" void kernel_launch(void* const* d_in, const int* in_sizes, int n_in,
                              void* d_out, int out_size)
{
    (void)in_sizes; (void)n_in; (void)out_size;
    const float* x        = (const float*)d_in[0];
    const float* h_in_w   = (const float*)d_in[1];
    const float* h_conv_w = (const float*)d_in[2];
    const float* h_conv_b = (const float*)d_in[3];
    const float* h_A_log  = (const float*)d_in[4];
    const float* h_dt_b   = (const float*)d_in[5];
    const float* h_D      = (const float*)d_in[6];
    const float* h_norm_w = (const float*)d_in[7];
    const float* h_out_w  = (const float*)d_in[8];
    const float* v_in_w   = (const float*)d_in[9];
    const float* v_conv_w = (const float*)d_in[10];
    const float* v_conv_b = (const float*)d_in[11];
    const float* v_A_log  = (const float*)d_in[12];
    const float* v_dt_b   = (const float*)d_in[13];
    const float* v_D      = (const float*)d_in[14];
    const float* v_norm_w = (const float*)d_in[15];
    const float* v_out_w  = (const float*)d_in[16];
    const float* fc_w     = (const float*)d_in[17];
    const float* fc_b     = (const float*)d_in[18];
    float* out = (float*)d_out;

    float *zx, *xbc, *y, *hout, *vout, *fceff;
    __half *asplit, *wsplit;
    cudaGetSymbolAddress((void**)&zx,     g_zx);
    cudaGetSymbolAddress((void**)&xbc,    g_xbc);
    cudaGetSymbolAddress((void**)&y,      g_y);
    cudaGetSymbolAddress((void**)&hout,   g_hout);
    cudaGetSymbolAddress((void**)&vout,   g_vout);
    cudaGetSymbolAddress((void**)&fceff,  g_fceff);
    cudaGetSymbolAddress((void**)&asplit, g_asplit);
    cudaGetSymbolAddress((void**)&wsplit, g_wsplit);

    cudaFuncSetAttribute(ssm_kernel, cudaFuncAttributeMaxDynamicSharedMemorySize,
                         SSM_SMEM_BYTES);
    cudaFuncSetAttribute(gemm_tc_kernel, cudaFuncAttributeMaxDynamicSharedMemorySize,
                         GSM_TOTAL);

    const int TPB = 256;
    for (int dir = 0; dir < 2; ++dir) {
        const float* in_w   = dir ? v_in_w   : h_in_w;
        const float* conv_w = dir ? v_conv_w : h_conv_w;
        const float* conv_b = dir ? v_conv_b : h_conv_b;
        const float* A_log  = dir ? v_A_log  : h_A_log;
        const float* dt_b   = dir ? v_dt_b   : h_dt_b;
        const float* Dp     = dir ? v_D      : h_D;
        const float* norm_w = dir ? v_norm_w : h_norm_w;
        const float* out_w  = dir ? v_out_w  : h_out_w;
        float* dirout       = dir ? vout     : hout;

        // in-proj: split + mma GEMM (K2=1024, N=2320 padded 2432)
        if (dir == 0)
            split_act_h_kernel<<<(NTOK * 512 + TPB - 1) / TPB, TPB>>>(x, asplit);
        else
            split_act_v_kernel<<<(NTOK * 512 + TPB - 1) / TPB, TPB>>>(x, asplit);
        split_w_kernel<<<(NPAD_IN * 512 + TPB - 1) / TPB, TPB>>>(in_w, wsplit,
                                                                 D_IN_PROJ, NPAD_IN, 512);
        {
            dim3 g(NPAD_IN / 128, NTOK / 128);
            gemm_tc_kernel<<<g, 256, GSM_TOTAL>>>(asplit, wsplit, zx, 1024, D_IN_PROJ, nullptr);
        }

        conv_silu_kernel<<<(NSEQ * (CONV_DIM / 4) + TPB - 1) / TPB, TPB>>>(zx, conv_w, conv_b, xbc);
        ssm_kernel<<<NSEQ * NHEADS, 256, SSM_SMEM_BYTES>>>(zx, xbc, A_log, dt_b, Dp, y);
        gate_norm_split_kernel<<<NTOK, 256>>>(zx, norm_w, y, asplit);

        // out-proj: K2=2048, N=512
        split_w_kernel<<<(512 * 1024 + TPB - 1) / TPB, TPB>>>(out_w, wsplit, 512, 512, 1024);
        {
            dim3 g(512 / 128, NTOK / 128);
            gemm_tc_kernel<<<g, 256, GSM_TOTAL>>>(asplit, wsplit, dirout, 2048, 512, nullptr);
        }
    }

    // final fc: cat + split, pre-summed weights, bias
    cat_split_kernel<<<((size_t)NTOK * D_INNER + TPB - 1) / TPB, TPB>>>(vout, hout, asplit);
    fceff_kernel<<<(D_MODEL * D_INNER + TPB - 1) / TPB, TPB>>>(fc_w, fceff);
    split_w_kernel<<<(512 * 1024 + TPB - 1) / TPB, TPB>>>(fceff, wsplit, 512, 512, 1024);
    {
        dim3 g(512 / 128, NTOK / 128);
        gemm_tc_kernel<<<g, 256, GSM_TOTAL>>>(asplit, wsplit, out, 2048, 512, fc_b);
    }
}